// round 6
// baseline (speedup 1.0000x reference)
#include <cuda_runtime.h>

// Problem constants
#define BB     64
#define LL     512
#define NCH    64
#define AA     64
#define DD     256
#define PP     16
#define SBASE  8
#define MAXOFF 4.0f

#define NCHUNK 8
#define LCHUNK 64   // LL / NCHUNK

// Partial pooled sums: [b][chunk][32]  (deterministic, no atomics)
__device__ float g_part[BB * NCHUNK * 32];
// Sampling params per (b,a,p)
__device__ int   g_i0[BB * AA * PP];
__device__ float g_f [BB * AA * PP];

// ---------------------------------------------------------------------------
// packed f32x2 helpers (sm_100a)
// ---------------------------------------------------------------------------
__device__ __forceinline__ unsigned long long pack2(float lo, float hi) {
    unsigned long long r;
    asm("mov.b64 %0, {%1, %2};" : "=l"(r) : "f"(lo), "f"(hi));
    return r;
}
__device__ __forceinline__ float2 unpack2(unsigned long long v) {
    float2 r;
    asm("mov.b64 {%0, %1}, %2;" : "=f"(r.x), "=f"(r.y) : "l"(v));
    return r;
}
__device__ __forceinline__ unsigned long long fma2(unsigned long long a,
                                                   unsigned long long b,
                                                   unsigned long long c) {
    unsigned long long d;
    asm("fma.rn.f32x2 %0, %1, %2, %3;" : "=l"(d) : "l"(a), "l"(b), "l"(c));
    return d;
}

// ---------------------------------------------------------------------------
// Kernel 1: conv1d(N->32,k=3,pad=1) + ReLU + partial mean-pool
// grid: (NCHUNK, B), block: 128 threads = 8 o-groups x 16 l-groups.
// Vectorized SMEM layouts: x as [n][l] (pitch 68), w as [n][k][o] (pitch 32).
// Inner loop: 2+3 vector LDS + 48 FMA.
// ---------------------------------------------------------------------------
__global__ __launch_bounds__(128) void k_convpool(
    const float* __restrict__ x,       // (B, L, N)
    const float* __restrict__ conv_w,  // (32, N, 3)
    const float* __restrict__ conv_b)  // (32)
{
    const int c = blockIdx.x, b = blockIdx.y;
    const int tid = threadIdx.x;
    const int og = tid & 7;      // 0..7
    const int lg = tid >> 3;     // 0..15
    const int o0 = og * 4;

    __shared__ float sx[64 * 68];       // [n][r], r = 0..65, pitch 68
    __shared__ float sw2[64 * 96];      // [n][k][o] : n*96 + k*32 + o
    __shared__ float sred[32][17];

    const int L0 = c * LCHUNK;

    // load x slab: row r <-> gl = L0-1+r ; coalesced over n
    for (int i = tid; i < 66 * 64; i += 128) {
        int r = i >> 6, n = i & 63;
        int gl = L0 - 1 + r;
        float v = 0.f;
        if (gl >= 0 && gl < LL) v = x[(b * LL + gl) * NCH + n];
        sx[n * 68 + r] = v;
    }
    // load conv weights transposed: sw2[(n*3+k)*32 + o] = conv_w[o*192 + n*3 + k]
    for (int i = tid; i < 6144; i += 128) {
        int o = i & 31, t = i >> 5;     // t = n*3 + k
        sw2[i] = conv_w[o * 192 + t];
    }
    __syncthreads();

    float acc[4][4];
#pragma unroll
    for (int o = 0; o < 4; o++)
#pragma unroll
        for (int dl = 0; dl < 4; dl++) acc[o][dl] = 0.f;

    const int lbase = lg * 4;
#pragma unroll 4
    for (int n = 0; n < 64; n++) {
        float xv[6];
        {
            float4 xa = *(const float4*)&sx[n * 68 + lbase];
            float2 xb2 = *(const float2*)&sx[n * 68 + lbase + 4];
            xv[0] = xa.x; xv[1] = xa.y; xv[2] = xa.z; xv[3] = xa.w;
            xv[4] = xb2.x; xv[5] = xb2.y;
        }
        float4 w0 = *(const float4*)&sw2[n * 96 + 0 * 32 + o0];
        float4 w1 = *(const float4*)&sw2[n * 96 + 1 * 32 + o0];
        float4 w2 = *(const float4*)&sw2[n * 96 + 2 * 32 + o0];
        const float w0a[4] = {w0.x, w0.y, w0.z, w0.w};
        const float w1a[4] = {w1.x, w1.y, w1.z, w1.w};
        const float w2a[4] = {w2.x, w2.y, w2.z, w2.w};
#pragma unroll
        for (int o = 0; o < 4; o++) {
#pragma unroll
            for (int dl = 0; dl < 4; dl++) {
                float t = acc[o][dl];
                t = fmaf(xv[dl],     w0a[o], t);
                t = fmaf(xv[dl + 1], w1a[o], t);
                t = fmaf(xv[dl + 2], w2a[o], t);
                acc[o][dl] = t;
            }
        }
    }

    // bias + ReLU + sum over this thread's 4 l's
#pragma unroll
    for (int o = 0; o < 4; o++) {
        float cb = conv_b[o0 + o];
        float s = 0.f;
#pragma unroll
        for (int dl = 0; dl < 4; dl++) s += fmaxf(acc[o][dl] + cb, 0.f);
        sred[o0 + o][lg] = s;
    }
    __syncthreads();

    if (tid < 32) {
        float s = 0.f;
#pragma unroll
        for (int j = 0; j < 16; j++) s += sred[tid][j];
        g_part[(b * NCHUNK + c) * 32 + tid] = s;
    }
}

// ---------------------------------------------------------------------------
// Kernel 1b: delta -> per-(b,a,p) sampling indices + fractions
// ---------------------------------------------------------------------------
__global__ __launch_bounds__(64) void k_delta(
    const float* __restrict__ lin_w,  // (A, 32)
    const float* __restrict__ lin_b)  // (A)
{
    const int b = blockIdx.x;
    const int a = threadIdx.x;

    __shared__ float pooled[32];
    if (a < 32) {
        float s = 0.f;
#pragma unroll
        for (int c = 0; c < NCHUNK; c++)
            s += g_part[(b * NCHUNK + c) * 32 + a];
        pooled[a] = s * (1.0f / (float)LL);
    }
    __syncthreads();

    float v = lin_b[a];
#pragma unroll
    for (int k = 0; k < 32; k++)
        v = fmaf(pooled[k], lin_w[a * 32 + k], v);
    float deltav = MAXOFF * tanhf(v);

    const int base = (b * AA + a) * PP;
#pragma unroll
    for (int p = 0; p < PP; p++) {
        float xs = (float)(a * SBASE) + deltav + ((float)p - 7.5f);
        xs = fminf(fmaxf(xs, 0.0f), (float)(LL - 1));
        float fl = floorf(xs);
        g_i0[base + p] = (int)fl;
        g_f [base + p] = xs - fl;
    }
}

// ---------------------------------------------------------------------------
// Kernel 2: bilinear gather -> patch projection (P->D) -> out
// grid: B*A blocks, 256 threads, 2 CTAs/SM (128-reg budget, no spills).
// Thread owns a d-QUAD (32 packed weight regs), 16 n-iters, STG.128 stores.
// ---------------------------------------------------------------------------
__global__ __launch_bounds__(256, 2) void k_main(
    const float* __restrict__ x,      // (B, L, N)
    const float* __restrict__ wp_w,   // (D, P)
    const float* __restrict__ wp_b,   // (D)
    float* __restrict__ out)          // (B*N, A, D)
{
    const int bx = blockIdx.x;
    const int b = bx >> 6, a = bx & 63;
    const int tid = threadIdx.x;

    __shared__ float samp[64 * 20];   // [n][p], pitch 20 floats
    __shared__ int   si0[PP];
    __shared__ float sf[PP];

    // ---- Phase A: fetch sampling params ----
    if (tid < PP) {
        si0[tid] = g_i0[(b * AA + a) * PP + tid];
        sf[tid]  = g_f [(b * AA + a) * PP + tid];
    }
    __syncthreads();

    // ---- Phase B: bilinear gather into SMEM ----
    {
        const int n = tid & 63, pg = tid >> 6;   // 4 p's each
        const float* xb = x + (size_t)b * (LL * NCH) + n;
        float tmp[4];
#pragma unroll
        for (int j = 0; j < 4; j++) {
            int p = pg * 4 + j;
            int i0 = si0[p];
            int i1 = min(i0 + 1, LL - 1);
            float g0 = xb[(size_t)i0 * NCH];
            float g1 = xb[(size_t)i1 * NCH];
            tmp[j] = fmaf(sf[p], g1 - g0, g0);
        }
        *(float4*)&samp[n * 20 + pg * 4] =
            make_float4(tmp[0], tmp[1], tmp[2], tmp[3]);
    }
    __syncthreads();

    // ---- Phase C: patch projection; thread owns d-quad, 16 n-iters ----
    const int dq = tid & 63;             // d-quad index 0..63
    const int ng = tid >> 6;             // 0..3
    const int d0 = dq * 4;

    unsigned long long w2[4][8];
    float wb[4];
#pragma unroll
    for (int d = 0; d < 4; d++) {
        const float4* wrow = (const float4*)(wp_w + (size_t)(d0 + d) * PP);
#pragma unroll
        for (int q = 0; q < 4; q++) {
            float4 v = wrow[q];
            w2[d][2 * q]     = pack2(v.x, v.y);
            w2[d][2 * q + 1] = pack2(v.z, v.w);
        }
        wb[d] = wp_b[d0 + d];
    }

    float* outb = out + ((size_t)(b * 64) * 64 + a) * 256 + d0;

    for (int n = ng; n < 64; n += 4) {
        const ulonglong2* sv = (const ulonglong2*)&samp[n * 20];
        ulonglong2 v0 = sv[0], v1 = sv[1], v2v = sv[2], v3 = sv[3];
        unsigned long long sp[8] = {v0.x, v0.y, v1.x, v1.y,
                                    v2v.x, v2v.y, v3.x, v3.y};
        unsigned long long acc[4] = {0ull, 0ull, 0ull, 0ull};
#pragma unroll
        for (int q = 0; q < 8; q++) {
#pragma unroll
            for (int d = 0; d < 4; d++)
                acc[d] = fma2(sp[q], w2[d][q], acc[d]);
        }
        float4 r;
        {
            float2 a0 = unpack2(acc[0]);
            float2 a1 = unpack2(acc[1]);
            float2 a2 = unpack2(acc[2]);
            float2 a3 = unpack2(acc[3]);
            r.x = a0.x + a0.y + wb[0];
            r.y = a1.x + a1.y + wb[1];
            r.z = a2.x + a2.y + wb[2];
            r.w = a3.x + a3.y + wb[3];
        }
        *(float4*)&outb[(size_t)n * (64 * 256)] = r;
    }
}

// ---------------------------------------------------------------------------
extern "C" void kernel_launch(void* const* d_in, const int* in_sizes, int n_in,
                              void* d_out, int out_size)
{
    const float* x      = (const float*)d_in[0];
    const float* conv_w = (const float*)d_in[1];
    const float* conv_b = (const float*)d_in[2];
    const float* lin_w  = (const float*)d_in[3];
    const float* lin_b  = (const float*)d_in[4];
    const float* wp_w   = (const float*)d_in[5];
    const float* wp_b   = (const float*)d_in[6];
    float* out = (float*)d_out;

    k_convpool<<<dim3(NCHUNK, BB), 128>>>(x, conv_w, conv_b);
    k_delta<<<BB, 64>>>(lin_w, lin_b);
    k_main<<<BB * AA, 256>>>(x, wp_w, wp_b, out);
}